// round 8
// baseline (speedup 1.0000x reference)
#include <cuda_runtime.h>
#include <cuda_bf16.h>
#include <cuda_fp16.h>
#include <cstdint>

// Problem constants
#define BB 8
#define TT 128
#define SS 512
#define DD 128
#define CLUSTER 8
#define SSLICE (SS / CLUSTER)   // 64 encoder rows per rank
#define NTHR 512
#define NWARP 16

// Scratch (allocation-free rule: __device__ globals)
__device__ float g_HU[BB * SS * DD];   // H @ Ua, [B,S,D]
__device__ float g_XG[BB * TT * 512];  // x@W + bias for 4 gates (i,f,c,o), [B,T,512]

__device__ __forceinline__ float4 ldg4(const float* p) {
    return __ldg(reinterpret_cast<const float4*>(p));
}
__device__ __forceinline__ uint32_t smem_u32(const void* p) {
    uint32_t a;
    asm("{ .reg .u64 t; cvta.to.shared.u64 t, %1; cvt.u32.u64 %0, t; }" : "=r"(a) : "l"(p));
    return a;
}
// st.async a float to the SAME smem offset on cluster CTA `rank`, completing
// tx bytes on that rank's mbarrier.
__device__ __forceinline__ void st_async_remote(uint32_t laddr, uint32_t lmbar,
                                                uint32_t rank, float v) {
    uint32_t ra, rb;
    asm volatile("mapa.shared::cluster.u32 %0, %1, %2;" : "=r"(ra) : "r"(laddr), "r"(rank));
    asm volatile("mapa.shared::cluster.u32 %0, %1, %2;" : "=r"(rb) : "r"(lmbar), "r"(rank));
    asm volatile("st.async.shared::cluster.mbarrier::complete_tx::bytes.b32 [%0], %1, [%2];"
                 :: "r"(ra), "r"(__float_as_uint(v)), "r"(rb) : "memory");
}
// 16-byte packed variant: 4 floats per DSMEM message.
__device__ __forceinline__ void st_async_remote_v4(uint32_t laddr, uint32_t lmbar,
                                                   uint32_t rank, float a, float b,
                                                   float c, float d) {
    uint32_t ra, rb;
    asm volatile("mapa.shared::cluster.u32 %0, %1, %2;" : "=r"(ra) : "r"(laddr), "r"(rank));
    asm volatile("mapa.shared::cluster.u32 %0, %1, %2;" : "=r"(rb) : "r"(lmbar), "r"(rank));
    asm volatile("st.async.shared::cluster.mbarrier::complete_tx::bytes.v4.b32 "
                 "[%0], {%1, %2, %3, %4}, [%5];"
                 :: "r"(ra), "r"(__float_as_uint(a)), "r"(__float_as_uint(b)),
                    "r"(__float_as_uint(c)), "r"(__float_as_uint(d)), "r"(rb) : "memory");
}
__device__ __forceinline__ void mbar_init(uint32_t addr, uint32_t count) {
    asm volatile("mbarrier.init.shared.b64 [%0], %1;" :: "r"(addr), "r"(count) : "memory");
}
__device__ __forceinline__ void mbar_expect_tx(uint32_t addr, uint32_t bytes) {
    asm volatile("mbarrier.arrive.expect_tx.shared.b64 _, [%0], %1;"
                 :: "r"(addr), "r"(bytes) : "memory");
}
__device__ __forceinline__ void mbar_wait(uint32_t addr, uint32_t parity) {
    uint32_t done;
    asm volatile(
        "{\n\t.reg .pred p;\n\t"
        "mbarrier.try_wait.parity.acquire.cta.shared::cta.b64 p, [%1], %2;\n\t"
        "selp.b32 %0, 1, 0, p;\n\t}"
        : "=r"(done) : "r"(addr), "r"(parity) : "memory");
    if (!done) {
        asm volatile(
            "{\n\t.reg .pred P1;\n\t"
            "WL_%=:\n\t"
            "mbarrier.try_wait.parity.acquire.cta.shared::cta.b64 P1, [%0], %1, 0x989680;\n\t"
            "@P1 bra.uni WD_%=;\n\t"
            "bra.uni WL_%=;\n\t"
            "WD_%=:\n\t}"
            :: "r"(addr), "r"(parity) : "memory");
    }
}
#define CLUSTER_SYNC() do { \
    asm volatile("barrier.cluster.arrive.aligned;" ::: "memory"); \
    asm volatile("barrier.cluster.wait.aligned;"   ::: "memory"); \
} while (0)

// ---------------------------------------------------------------------------
// Merged precompute kernel (one launch, full chip):
//   blocks [0,512):    HU[b,s,e] = sum_d H[b,s,d] * Ua[d,e]   (8 rows/block)
//   blocks [512,1024): XG[row, g*128+c] = b_g[c] + sum_k x[row,k]*W_g[k,c]
// ---------------------------------------------------------------------------
__global__ __launch_bounds__(128) void pre_kernel(
    const float* __restrict__ H, const float* __restrict__ Ua,
    const float* __restrict__ x,
    const float* __restrict__ Wi, const float* __restrict__ Wf,
    const float* __restrict__ Wc, const float* __restrict__ Wo,
    const float* __restrict__ bi, const float* __restrict__ bf,
    const float* __restrict__ bc, const float* __restrict__ bo) {
    __shared__ __align__(16) float sA[8 * DD];
    const int tid = threadIdx.x;
    const int blk = blockIdx.x;

    const float* Asrc;
    const float* W;
    float bias = 0.f;
    float* dst;
    int dstride;
    if (blk < 512) {
        Asrc = H + (size_t)blk * 8 * DD;
        W = Ua;
        dst = g_HU + (size_t)blk * 8 * DD;
        dstride = DD;
    } else {
        const int idx = blk - 512;
        const int g = idx >> 7, rb = idx & 127;
        Asrc = x + (size_t)rb * 8 * DD;
        W = (g == 0) ? Wi : (g == 1) ? Wf : (g == 2) ? Wc : Wo;
        const float* bb = (g == 0) ? bi : (g == 1) ? bf : (g == 2) ? bc : bo;
        bias = __ldg(bb + tid);
        dst = g_XG + (size_t)rb * 8 * 512 + g * DD;
        dstride = 512;
    }
    #pragma unroll
    for (int i = 0; i < 8; i++) sA[i * DD + tid] = __ldg(Asrc + i * DD + tid);
    __syncthreads();

    float acc[8];
    #pragma unroll
    for (int r = 0; r < 8; r++) acc[r] = bias;
    #pragma unroll 4
    for (int k0 = 0; k0 < DD; k0 += 4) {
        const float w0 = __ldg(W + (k0 + 0) * DD + tid);
        const float w1 = __ldg(W + (k0 + 1) * DD + tid);
        const float w2 = __ldg(W + (k0 + 2) * DD + tid);
        const float w3 = __ldg(W + (k0 + 3) * DD + tid);
        #pragma unroll
        for (int r = 0; r < 8; r++) {
            const float4 a = *reinterpret_cast<const float4*>(&sA[r * DD + k0]);
            acc[r] += a.x * w0 + a.y * w1 + a.z * w2 + a.w * w3;
        }
    }
    #pragma unroll
    for (int r = 0; r < 8; r++) dst[r * dstride + tid] = acc[r];
}

// ---------------------------------------------------------------------------
// Recurrent kernel: 8 clusters x 8 CTAs, ONE batch per cluster. Rank r:
//   - attention over encoder rows [64r, 64r+64)  (HU, H slices in smem)
//   - gate (r>>1), columns [(r&1)*64, +64)       (U, C in registers)
// f16x2 tanh in the score kernel (MUFU floor halved); 2-stage parallel
// partial reductions; packed st.async.v4 exchanges + mbarrier.
// ---------------------------------------------------------------------------
// dynamic smem layout (floats):
//   sHU   [0     ,  8192)   HU slice (64 x 128)
//   sH    [8192  , 16384)   H slice
//   sh    [16384 , 16512)
//   scell [16512 , 16640)
//   sq    [16640 , 16768)
//   sctx  [16768 , 16896)   UNNORMALIZED ctx sum
//   part  [16896 , 18944)   16 x 128 ctx warp partials
//   part2 [18944 , 19456)   4 x 128 stage-1 sums
//   zred  [19456 , 19473)   16 warp z partials + total at [16]
//   ctxbuf[19476 , 20532)   8 x 132 mailbox (ctx[128] + z at [128])
//   gbuf  [20532 , 21044)   4 x 128 gate mailbox
//   mbars [21044 , 21048)   2 x u64 (ctx, gate)
//   invZ  [21048 , 21049)
#define SM_FLOATS 21052

__global__ __launch_bounds__(NTHR, 1) __cluster_dims__(CLUSTER, 1, 1)
void rec_kernel(const float* __restrict__ H, const float* __restrict__ init,
                const float* __restrict__ Wa, const float* __restrict__ v,
                const float* __restrict__ Ui, const float* __restrict__ Ci,
                const float* __restrict__ Uf, const float* __restrict__ Cf,
                const float* __restrict__ Uc, const float* __restrict__ Cc,
                const float* __restrict__ Uo, const float* __restrict__ Co,
                float* __restrict__ out) {
    extern __shared__ __align__(16) float dsm[];
    float* sHU    = dsm;
    float* sHs    = dsm + 8192;
    float* sh     = dsm + 16384;
    float* scell  = dsm + 16512;
    float* sq     = dsm + 16640;
    float* sctx   = dsm + 16768;
    float* part   = dsm + 16896;
    float* part2  = dsm + 18944;
    float* zred   = dsm + 19456;
    float* ctxbuf = dsm + 19476;
    float* gbuf   = dsm + 20532;
    float* mbars  = dsm + 21044;
    float* s_invZ = dsm + 21048;

    const int tid  = threadIdx.x;
    const int lane = tid & 31;
    const int wp   = tid >> 5;
    const int b    = blockIdx.x >> 3;   // batch
    const int rk   = blockIdx.x & 7;    // cluster rank

    const uint32_t ctx_mbar  = smem_u32(&mbars[0]);
    const uint32_t gate_mbar = smem_u32(&mbars[2]);

    // ---------------- prologue ----------------
    if (tid == 0) {
        mbar_init(ctx_mbar, 1);
        mbar_init(gate_mbar, 1);
        asm volatile("fence.mbarrier_init.release.cluster;" ::: "memory");
    }
    {
        const float4* HUsrc = (const float4*)(g_HU + (size_t)(b * SS + rk * SSLICE) * DD);
        const float4* Hsrc  = (const float4*)(H    + (size_t)(b * SS + rk * SSLICE) * DD);
        float4* dHU = (float4*)sHU;
        float4* dH  = (float4*)sHs;
        #pragma unroll
        for (int i = 0; i < 4; i++) {
            dHU[tid + i * NTHR] = HUsrc[tid + i * NTHR];
            dH[tid + i * NTHR]  = Hsrc[tid + i * NTHR];
        }
        if (tid < DD) {
            sh[tid]    = init[b * DD + tid];
            scell[tid] = init[BB * DD + b * DD + tid];
        }
    }

    // v cached per-lane: f32x4 for fallback, f16x2 pair for the tanh dot
    const float4 vreg = ldg4(v + 4 * lane);
    const __half2 v01 = __floats2half2_rn(vreg.x, vreg.y);
    const __half2 v23 = __floats2half2_rn(vreg.z, vreg.w);

    // P1 layout: warp wp -> q cols [8wp,8wp+8); col = 8wp+(lane&7), part qp=lane>>3
    const int qcol = (wp << 3) + (lane & 7);
    const int qp   = lane >> 3;
    float waReg[32];
    #pragma unroll
    for (int kk = 0; kk < 32; kk++)
        waReg[kk] = __ldg(Wa + (qp + 4 * kk) * DD + qcol);

    // gate layout: gate = rk>>1, cols gc0+[0,64); col = gc0+(tid>>3), part gp=tid&7
    const int gate = rk >> 1;
    const int gc0  = (rk & 1) * 64;
    const int gcol = gc0 + (tid >> 3);
    const int gp   = tid & 7;
    const float* Ug = (gate == 0) ? Ui : (gate == 1) ? Uf : (gate == 2) ? Uc : Uo;
    const float* Cg = (gate == 0) ? Ci : (gate == 1) ? Cf : (gate == 2) ? Cc : Co;
    float Ureg[16], Creg[16];
    #pragma unroll
    for (int kk = 0; kk < 16; kk++) {
        const int k = gp + 8 * kk;
        Ureg[kk] = __ldg(Ug + k * DD + gcol);
        Creg[kk] = __ldg(Cg + k * DD + gcol);
    }

    const float* XGb = g_XG + (size_t)b * TT * 512;

    // Mailbox slot addresses (same smem offsets cluster-wide; sender-indexed).
    const uint32_t ctx_addr = (tid < DD) ? smem_u32(&ctxbuf[rk * 132 + tid]) : 0u;
    const uint32_t zsl_addr = smem_u32(&ctxbuf[rk * 132 + 128]);
    // gate: lane<8 of warp wp sends float4 for cols gc0+4wp+[0,4) to rank=lane.
    const uint32_t g_addr   = smem_u32(&gbuf[gate * DD + gc0 + 4 * wp]);

    __syncthreads();
    CLUSTER_SYNC();   // mbarriers + smem ready on every rank

    for (int t = 0; t < TT; t++) {
        const uint32_t parity = (uint32_t)(t & 1);
        if (tid == 0) {
            mbar_expect_tx(ctx_mbar,  CLUSTER * 129 * 4);
            mbar_expect_tx(gate_mbar, 512 * 4);
        }
        // prefetch this step's x-gate contribution
        const float xg = __ldg(XGb + t * 512 + gate * DD + gcol);

        // ---------- P1: q = h @ Wa (regs) + hoisted h@U gate partial ----------
        float hu;
        {
            float accq = 0.f, huv = 0.f;
            #pragma unroll
            for (int kk = 0; kk < 32; kk++) accq += sh[qp + 4 * kk] * waReg[kk];
            #pragma unroll
            for (int kk = 0; kk < 16; kk++) huv += sh[gp + 8 * kk] * Ureg[kk];
            hu = huv;
            accq += __shfl_xor_sync(0xffffffffu, accq, 8);
            accq += __shfl_xor_sync(0xffffffffu, accq, 16);
            if (lane < 8) sq[(wp << 3) + lane] = accq;
        }
        __syncthreads();  // A

        // ---------- P2: scores (f16x2 tanh) -> exp -> ctx partial ----------
        // no-max softmax: |score| <= sum|v| ~ 5, exp is safe in fp32.
        {
            const float4 q4 = *reinterpret_cast<const float4*>(&sq[lane * 4]);
            float4 ctx4 = make_float4(0.f, 0.f, 0.f, 0.f);
            float zp = 0.f;
            #pragma unroll
            for (int i = 0; i < 4; i++) {
                const int s = wp + (i << 4);
                const float4 hu4 = *reinterpret_cast<const float4*>(&sHU[s * DD + lane * 4]);
                const __half2 a01 = __floats2half2_rn(hu4.x + q4.x, hu4.y + q4.y);
                const __half2 a23 = __floats2half2_rn(hu4.z + q4.z, hu4.w + q4.w);
                uint32_t t01, t23;
                asm("tanh.approx.f16x2 %0, %1;"
                    : "=r"(t01) : "r"(*reinterpret_cast<const uint32_t*>(&a01)));
                asm("tanh.approx.f16x2 %0, %1;"
                    : "=r"(t23) : "r"(*reinterpret_cast<const uint32_t*>(&a23)));
                const __half2 m = __hfma2(*reinterpret_cast<const __half2*>(&t01), v01,
                                  __hmul2(*reinterpret_cast<const __half2*>(&t23), v23));
                float sc = __low2float(m) + __high2float(m);
                #pragma unroll
                for (int o = 16; o > 0; o >>= 1) sc += __shfl_xor_sync(0xffffffffu, sc, o);
                const float e = __expf(sc);
                zp += e;
                const float4 h4 = *reinterpret_cast<const float4*>(&sHs[s * DD + lane * 4]);
                ctx4.x += e * h4.x; ctx4.y += e * h4.y;
                ctx4.z += e * h4.z; ctx4.w += e * h4.w;
            }
            *reinterpret_cast<float4*>(&part[wp * DD + lane * 4]) = ctx4;
            if (lane == 0) zred[wp] = zp;
        }
        __syncthreads();  // B

        // ---------- 2-stage partial reduction (all 512 threads) ----------
        {
            const int d = tid & 127, grp = tid >> 7;
            const float* pr = part + 4 * grp * DD + d;
            part2[grp * DD + d] = pr[0] + pr[DD] + pr[2 * DD] + pr[3 * DD];
        }
        // z reduce via 16-lane shuffle tree (warp 15, lanes 0-15)
        if (wp == 15 && lane < 16) {
            float zz = zred[lane];
            #pragma unroll
            for (int o = 8; o > 0; o >>= 1) zz += __shfl_xor_sync(0x0000ffffu, zz, o);
            if (lane == 0) zred[16] = zz;
        }
        __syncthreads();  // B2

        // ---------- exchange 1: packed (ctx_r, z_r) -> all ranks ----------
        if (tid < DD) {
            float c = part2[tid] + part2[DD + tid] + part2[2 * DD + tid] + part2[3 * DD + tid];
            const float c1 = __shfl_down_sync(0xffffffffu, c, 1);
            const float c2 = __shfl_down_sync(0xffffffffu, c, 2);
            const float c3 = __shfl_down_sync(0xffffffffu, c, 3);
            if ((lane & 3) == 0) {
                #pragma unroll
                for (int q = 0; q < CLUSTER; q++)
                    st_async_remote_v4(ctx_addr, ctx_mbar, (uint32_t)q, c, c1, c2, c3);
            }
        } else if (tid == DD) {
            const float z = zred[16];
            #pragma unroll
            for (int q = 0; q < CLUSTER; q++)
                st_async_remote(zsl_addr, ctx_mbar, (uint32_t)q, z);
        }
        mbar_wait(ctx_mbar, parity);

        // ---------- combine: sctx = sum_r ctx_r (unnormalized); invZ once ----------
        if (tid < DD) {
            float c = 0.f;
            #pragma unroll
            for (int q = 0; q < CLUSTER; q++) c += ctxbuf[q * 132 + tid];
            sctx[tid] = c;
        } else if (tid == DD) {
            float Z = 0.f;
            #pragma unroll
            for (int q = 0; q < CLUSTER; q++) Z += ctxbuf[q * 132 + 128];
            s_invZ[0] = 1.f / Z;
        }
        __syncthreads();  // C

        // ---------- P4: gate slice; normalization folded into invZ multiply ----------
        {
            const float invZ = s_invZ[0];
            float acc = 0.f;
            #pragma unroll
            for (int kk = 0; kk < 16; kk++) acc += sctx[gp + 8 * kk] * Creg[kk];
            float p = hu + acc * invZ;
            p += __shfl_xor_sync(0xffffffffu, p, 1);
            p += __shfl_xor_sync(0xffffffffu, p, 2);
            p += __shfl_xor_sync(0xffffffffu, p, 4);
            const float pre = p + xg;
            const float act = (gate == 2) ? tanhf(pre) : 1.f / (1.f + __expf(-pre));
            // pack 4 consecutive cols (one per 8-lane subgroup) and ship to rank=lane
            const float a1 = __shfl_xor_sync(0xffffffffu, act, 8);
            const float a2 = __shfl_xor_sync(0xffffffffu, act, 16);
            const float a3 = __shfl_xor_sync(0xffffffffu, act, 24);
            if (lane < 8)
                st_async_remote_v4(g_addr, gate_mbar, (uint32_t)lane, act, a1, a2, a3);
        }
        mbar_wait(gate_mbar, parity);

        // ---------- LSTM update (duplicated on every rank) ----------
        if (tid < DD) {
            const float ig = gbuf[tid];
            const float fg = gbuf[DD + tid];
            const float gw = gbuf[2 * DD + tid];
            const float og = gbuf[3 * DD + tid];
            const float cn = fg * scell[tid] + ig * gw;
            const float hn = og * tanhf(cn);
            scell[tid] = cn;
            sh[tid]    = hn;
            if (rk == 0) out[(size_t)(b * TT + t) * DD + tid] = hn;
        }
        __syncthreads();  // D
    }
}

// ---------------------------------------------------------------------------
extern "C" void kernel_launch(void* const* d_in, const int* in_sizes, int n_in,
                              void* d_out, int out_size) {
    const float* x    = (const float*)d_in[0];
    const float* H    = (const float*)d_in[1];
    const float* init = (const float*)d_in[2];
    const float* Wa   = (const float*)d_in[3];
    const float* Ua   = (const float*)d_in[4];
    const float* v    = (const float*)d_in[5];
    const float* Wi   = (const float*)d_in[6];
    const float* Ui   = (const float*)d_in[7];
    const float* Ci   = (const float*)d_in[8];
    const float* bi   = (const float*)d_in[9];
    const float* Wf   = (const float*)d_in[10];
    const float* Uf   = (const float*)d_in[11];
    const float* Cf   = (const float*)d_in[12];
    const float* bf   = (const float*)d_in[13];
    const float* Wc   = (const float*)d_in[14];
    const float* Uc   = (const float*)d_in[15];
    const float* Cc   = (const float*)d_in[16];
    const float* bc   = (const float*)d_in[17];
    const float* Wo   = (const float*)d_in[18];
    const float* Uo   = (const float*)d_in[19];
    const float* Co   = (const float*)d_in[20];
    const float* bo   = (const float*)d_in[21];
    float* out = (float*)d_out;

    static bool attr_set = false;
    if (!attr_set) {
        cudaFuncSetAttribute(rec_kernel,
                             cudaFuncAttributeMaxDynamicSharedMemorySize,
                             SM_FLOATS * sizeof(float));
        attr_set = true;
    }

    pre_kernel<<<1024, 128>>>(H, Ua, x, Wi, Wf, Wc, Wo, bi, bf, bc, bo);
    rec_kernel<<<BB * CLUSTER, NTHR, SM_FLOATS * sizeof(float)>>>(
        H, init, Wa, v, Ui, Ci, Uf, Cf, Uc, Cc, Uo, Co, out);
}